// round 13
// baseline (speedup 1.0000x reference)
#include <cuda_runtime.h>
#include <cuda_fp16.h>

#define FULL 0xffffffffu
typedef unsigned long long ull;
typedef unsigned int uint;

__device__ __forceinline__ float relu_(float v) { return fmaxf(v, 0.0f); }

__device__ __forceinline__ ull ffma2(ull a, ull b, ull c) {
    ull d; asm("fma.rn.f32x2 %0, %1, %2, %3;" : "=l"(d) : "l"(a), "l"(b), "l"(c)); return d;
}
__device__ __forceinline__ ull fadd2(ull a, ull b) {
    ull d; asm("add.rn.f32x2 %0, %1, %2;" : "=l"(d) : "l"(a), "l"(b)); return d;
}
__device__ __forceinline__ ull pk2(float lo, float hi) {
    ull r; asm("mov.b64 %0, {%1, %2};" : "=l"(r) : "f"(lo), "f"(hi)); return r;
}
__device__ __forceinline__ void upk2(ull v, float& lo, float& hi) {
    asm("mov.b64 {%0, %1}, %2;" : "=f"(lo), "=f"(hi) : "l"(v));
}
__device__ __forceinline__ ull relu2(ull v) {
    float lo, hi; upk2(v, lo, hi);
    return pk2(fmaxf(lo, 0.0f), fmaxf(hi, 0.0f));
}
__device__ __forceinline__ float hadd2(ull v) {
    float lo, hi; upk2(v, lo, hi); return lo + hi;
}

// fp16x2 pack (e0 -> lower 16 bits)
__device__ __forceinline__ uint pack_f16(float e0, float e1) {
    __half2 h = __floats2half2_rn(e0, e1);
    return *reinterpret_cast<uint*>(&h);
}
// relu in the fp16x2 domain
__device__ __forceinline__ uint hrelu2(uint v) {
    uint r; asm("max.f16x2 %0, %1, %2;" : "=r"(r) : "r"(v), "r"(0u)); return r;
}
__device__ __forceinline__ uint packrelu_f16(float e0, float e1) {
    return hrelu2(pack_f16(e0, e1));
}

// m16n8k16 fp16 MMA, in-place fp32 accumulate.
__device__ __forceinline__ void mma_f16(float4& d, uint a0, uint a1, uint a2, uint a3,
                                        uint b0, uint b1) {
    asm volatile(
        "mma.sync.aligned.m16n8k16.row.col.f32.f16.f16.f32 "
        "{%0,%1,%2,%3}, {%4,%5,%6,%7}, {%8,%9}, {%0,%1,%2,%3};"
        : "+f"(d.x), "+f"(d.y), "+f"(d.z), "+f"(d.w)
        : "r"(a0), "r"(a1), "r"(a2), "r"(a3), "r"(b0), "r"(b1));
}
// m16n8k16 fp16 MMA, SEPARATE C operand: D = A*B + C (no bias-init movs).
__device__ __forceinline__ float4 mma_f16_c(uint a0, uint a1, uint a2, uint a3,
                                            uint b0, uint b1,
                                            float c0, float c1, float c2, float c3) {
    float4 d;
    asm volatile(
        "mma.sync.aligned.m16n8k16.row.col.f32.f16.f16.f32 "
        "{%0,%1,%2,%3}, {%4,%5,%6,%7}, {%8,%9}, {%10,%11,%12,%13};"
        : "=f"(d.x), "=f"(d.y), "=f"(d.z), "=f"(d.w)
        : "r"(a0), "r"(a1), "r"(a2), "r"(a3), "r"(b0), "r"(b1),
          "f"(c0), "f"(c1), "f"(c2), "f"(c3));
    return d;
}

// ---------------- constant blob (tail weights; layout as rounds 7-12) ----------------
#define CW_TOTAL 4624
__constant__ __align__(16) float c_w[CW_TOTAL];
__device__   __align__(16) float g_blob[CW_TOTAL];

#define NROWS 65536
__device__ __align__(16) ull g_sum[NROWS * 8];

__global__ void pack_kernel(const float* __restrict__ oW1, const float* __restrict__ ob1,
                            const float* __restrict__ oW2, const float* __restrict__ ob2,
                            const float* __restrict__ oW3, const float* __restrict__ ob3,
                            const float* __restrict__ sW1, const float* __restrict__ sb1,
                            const float* __restrict__ sW2, const float* __restrict__ sb2,
                            const float* __restrict__ sW3, const float* __restrict__ sb3,
                            const float* __restrict__ gW1, const float* __restrict__ gb1,
                            const float* __restrict__ gW2, const float* __restrict__ gb2)
{
    const int gt = blockIdx.x * 256 + threadIdx.x;   // 0..2047
    if (gt < 128) {
        int tp = gt >> 3, d = (gt >> 1) & 3, e = gt & 1;
        g_blob[gt]        = oW1[d * 32 + 2 * tp + e];
        g_blob[1744 + gt] = sW1[d * 32 + 2 * tp + e];
    }
    if (gt >= 128 && gt < 160) {
        int t = gt - 128;
        g_blob[128 + t]  = ob1[t];
        g_blob[1184 + t] = ob2[t];
        g_blob[1872 + t] = sb1[t];
        g_blob[2928 + t] = sb2[t];
        g_blob[4512 + t] = gb1[t];
    }
    if (gt >= 160 && gt < 176) { g_blob[1728 + gt - 160] = ob3[gt - 160]; }
    if (gt >= 176 && gt < 192) { g_blob[3472 + gt - 176] = sb3[gt - 176]; }
    if (gt >= 192 && gt < 256) { g_blob[4544 + gt - 192] = gW2[gt - 192]; }
    if (gt >= 256 && gt < 258) { g_blob[4608 + gt - 256] = gb2[gt - 256]; }
    if (gt < 1024) {
        int j = gt >> 5, i = gt & 31;
        g_blob[160  + j * 32 + i] = oW2[i * 32 + j];
        g_blob[1904 + j * 32 + i] = sW2[i * 32 + j];
        g_blob[3488 + j * 32 + i] = gW1[i * 32 + j];
    }
    if (gt >= 1024 && gt < 1536) {
        int idx = gt - 1024;
        g_blob[1216 + idx] = oW3[idx];
        g_blob[2960 + idx] = sW3[idx];
    }
}

// ---------------- Kernel A: other-agent MLP on TENSOR pipe (fp16, 32 MMA/row) -------
// Bias folded into the first MMA of each tile chain via separate-C operand.
__global__ __launch_bounds__(128, 4)
void hmma_kernel(const float* __restrict__ x,
                 const int*   __restrict__ selp,
                 const float* __restrict__ oW1, const float* __restrict__ ob1,
                 const float* __restrict__ oW2, const float* __restrict__ ob2,
                 const float* __restrict__ oW3, const float* __restrict__ ob3)
{
    const int lane  = threadIdx.x & 31;
    const int warp  = threadIdx.x >> 5;
    const int gwarp = blockIdx.x * 4 + warp;      // 0..4095
    const int g  = lane >> 2;                      // 0..7
    const int tc = lane & 3;                       // 0..3
    const int sel = selp[0];
    const uint Z = 0u;

    // ---- B fragments (single fp16) ----
    uint B1[4];
    #pragma unroll
    for (int n = 0; n < 4; ++n) {
        float wa = 0.0f, wb = 0.0f;
        if (tc < 2) {
            wa = oW1[(2 * tc) * 32 + 8 * n + g];
            wb = oW1[(2 * tc + 1) * 32 + 8 * n + g];
        }
        B1[n] = pack_f16(wa, wb);
    }
    uint B2[4][2][2];
    #pragma unroll
    for (int n = 0; n < 4; ++n) {
        #pragma unroll
        for (int ks = 0; ks < 2; ++ks) {
            int c  = 8 * n + g;
            int k0 = 16 * ks + 2 * tc;
            B2[n][ks][0] = pack_f16(oW2[k0 * 32 + c],       oW2[(k0 + 1) * 32 + c]);
            B2[n][ks][1] = pack_f16(oW2[(k0 + 8) * 32 + c], oW2[(k0 + 9) * 32 + c]);
        }
    }
    uint B3[2][2][2];
    #pragma unroll
    for (int n = 0; n < 2; ++n) {
        #pragma unroll
        for (int ks = 0; ks < 2; ++ks) {
            int c  = 8 * n + g;
            int k0 = 16 * ks + 2 * tc;
            B3[n][ks][0] = pack_f16(oW3[k0 * 16 + c],       oW3[(k0 + 1) * 16 + c]);
            B3[n][ks][1] = pack_f16(oW3[(k0 + 8) * 16 + c], oW3[(k0 + 9) * 16 + c]);
        }
    }
    float2 bz1[4], bz2[4], bz3[2];
    #pragma unroll
    for (int n = 0; n < 4; ++n) {
        bz1[n] = *reinterpret_cast<const float2*>(ob1 + 8 * n + 2 * tc);
        bz2[n] = *reinterpret_cast<const float2*>(ob2 + 8 * n + 2 * tc);
    }
    #pragma unroll
    for (int n = 0; n < 2; ++n)
        bz3[n] = *reinterpret_cast<const float2*>(ob3 + 8 * n + 2 * tc);

    // per-lane x offsets (within a row of 128 floats)
    const int offA0 = (g) * 4 + (tc & 1) * 2;
    const int offB0 = (8 + g) * 4 + (tc & 1) * 2;
    const int offA1 = (16 + g) * 4 + (tc & 1) * 2;
    const int offB1 = (24 + g) * 4 + (tc & 1) * 2;

    const float* xr = x + (size_t)(gwarp * 16) * 128;

    // prefetch first row
    float2 nA0 = *reinterpret_cast<const float2*>(xr + offA0);
    float2 nB0 = *reinterpret_cast<const float2*>(xr + offB0);
    float2 nA1 = *reinterpret_cast<const float2*>(xr + offA1);
    float2 nB1 = *reinterpret_cast<const float2*>(xr + offB1);

    // ---- persistent row loop: 16 rows per warp ----
    for (int it = 0; it < 16; ++it) {
        const int row = gwarp * 16 + it;
        float2 cA[2] = { nA0, nA1 };
        float2 cB[2] = { nB0, nB1 };
        if (it < 15) {
            const float* xn = xr + 128;
            nA0 = *reinterpret_cast<const float2*>(xn + offA0);
            nB0 = *reinterpret_cast<const float2*>(xn + offB0);
            nA1 = *reinterpret_cast<const float2*>(xn + offA1);
            nB1 = *reinterpret_cast<const float2*>(xn + offB1);
        }
        xr += 128;

        float v00 = 0.f, v01 = 0.f, v10 = 0.f, v11 = 0.f;

        #pragma unroll
        for (int m = 0; m < 2; ++m) {
            uint a0 = pack_f16(cA[m].x, cA[m].y);
            uint a1 = pack_f16(cB[m].x, cB[m].y);

            // ---- G1: single MMA per n-tile, bias as separate C ----
            float4 D1[4];
            #pragma unroll
            for (int n = 0; n < 4; ++n)
                D1[n] = mma_f16_c(a0, a1, Z, Z, B1[n], Z,
                                  bz1[n].x, bz1[n].y, bz1[n].x, bz1[n].y);

            // ---- G2: ks=0 carries bias via C; ks=1 accumulates in place ----
            uint A0 = packrelu_f16(D1[0].x, D1[0].y);
            uint A1 = packrelu_f16(D1[0].z, D1[0].w);
            uint A2 = packrelu_f16(D1[1].x, D1[1].y);
            uint A3 = packrelu_f16(D1[1].z, D1[1].w);
            float4 D2[4];
            #pragma unroll
            for (int n = 0; n < 4; ++n)
                D2[n] = mma_f16_c(A0, A1, A2, A3, B2[n][0][0], B2[n][0][1],
                                  bz2[n].x, bz2[n].y, bz2[n].x, bz2[n].y);
            A0 = packrelu_f16(D1[2].x, D1[2].y);
            A1 = packrelu_f16(D1[2].z, D1[2].w);
            A2 = packrelu_f16(D1[3].x, D1[3].y);
            A3 = packrelu_f16(D1[3].z, D1[3].w);
            #pragma unroll
            for (int n = 0; n < 4; ++n)
                mma_f16(D2[n], A0, A1, A2, A3, B2[n][1][0], B2[n][1][1]);

            // ---- G3: same pattern ----
            A0 = packrelu_f16(D2[0].x, D2[0].y);
            A1 = packrelu_f16(D2[0].z, D2[0].w);
            A2 = packrelu_f16(D2[1].x, D2[1].y);
            A3 = packrelu_f16(D2[1].z, D2[1].w);
            float4 D3[2];
            #pragma unroll
            for (int n = 0; n < 2; ++n)
                D3[n] = mma_f16_c(A0, A1, A2, A3, B3[n][0][0], B3[n][0][1],
                                  bz3[n].x, bz3[n].y, bz3[n].x, bz3[n].y);
            A0 = packrelu_f16(D2[2].x, D2[2].y);
            A1 = packrelu_f16(D2[2].z, D2[2].w);
            A2 = packrelu_f16(D2[3].x, D2[3].y);
            A3 = packrelu_f16(D2[3].z, D2[3].w);
            #pragma unroll
            for (int n = 0; n < 2; ++n)
                mma_f16(D3[n], A0, A1, A2, A3, B3[n][1][0], B3[n][1][1]);

            // epilogue: relu, mask selected agent, accumulate
            float mk0 = (m * 16 + g == sel) ? 0.0f : 1.0f;
            float mk1 = (m * 16 + 8 + g == sel) ? 0.0f : 1.0f;
            v00 += relu_(D3[0].x) * mk0 + relu_(D3[0].z) * mk1;
            v01 += relu_(D3[0].y) * mk0 + relu_(D3[0].w) * mk1;
            v10 += relu_(D3[1].x) * mk0 + relu_(D3[1].z) * mk1;
            v11 += relu_(D3[1].y) * mk0 + relu_(D3[1].w) * mk1;
        }

        ull p0 = pk2(v00, v01);
        ull p1 = pk2(v10, v11);
        #pragma unroll
        for (int off = 4; off < 32; off <<= 1) {
            p0 = fadd2(p0, __shfl_xor_sync(FULL, p0, off));
            p1 = fadd2(p1, __shfl_xor_sync(FULL, p1, off));
        }
        if (lane < 4) {
            g_sum[(size_t)row * 8 + tc]     = p0;
            g_sum[(size_t)row * 8 + 4 + tc] = p1;
        }
    }
}

// ---------------- Kernel B: tail (unchanged, full fp32) ----------------
__global__ __launch_bounds__(256)
void tail_kernel(const float* __restrict__ x,
                 const int*   __restrict__ selp,
                 float* __restrict__ out_q)
{
    const int row = blockIdx.x * 256 + threadIdx.x;
    const int sel = selp[0];

    const float4 xs = reinterpret_cast<const float4*>(x)[row * 32 + sel];

    ull so_p[8];
    {
        const ulonglong2* src = reinterpret_cast<const ulonglong2*>(g_sum + (size_t)row * 8);
        #pragma unroll
        for (int r = 0; r < 4; ++r) {
            ulonglong2 v = src[r];
            so_p[2 * r + 0] = v.x;
            so_p[2 * r + 1] = v.y;
        }
    }

    ull xd0 = pk2(xs.x, xs.x), xd1 = pk2(xs.y, xs.y);
    ull xd2 = pk2(xs.z, xs.z), xd3 = pk2(xs.w, xs.w);
    ull h1[16];
    {
        const ulonglong2* w1 = reinterpret_cast<const ulonglong2*>(c_w + 1744);
        const ull* b1 = reinterpret_cast<const ull*>(c_w + 1872);
        #pragma unroll
        for (int t = 0; t < 16; ++t) {
            ulonglong2 wA = w1[2 * t + 0];
            ulonglong2 wB = w1[2 * t + 1];
            ull a = ffma2(xd0, wA.x, b1[t]);
            a = ffma2(xd1, wA.y, a);
            a = ffma2(xd2, wB.x, a);
            a = ffma2(xd3, wB.y, a);
            h1[t] = relu2(a);
        }
    }

    ull acc3[8];
    {
        const ull* b3 = reinterpret_cast<const ull*>(c_w + 3472);
        #pragma unroll
        for (int t = 0; t < 8; ++t) acc3[t] = b3[t];
    }
    #pragma unroll 4
    for (int j = 0; j < 32; ++j) {
        ull a = 0ull;
        const ulonglong2* w2 = reinterpret_cast<const ulonglong2*>(c_w + 1904 + j * 32);
        #pragma unroll
        for (int q = 0; q < 8; ++q) {
            ulonglong2 w = w2[q];
            a = ffma2(h1[2 * q + 0], w.x, a);
            a = ffma2(h1[2 * q + 1], w.y, a);
        }
        float s = relu_(hadd2(a) + c_w[2928 + j]);
        ull p = pk2(s, s);
        const ulonglong2* w3 = reinterpret_cast<const ulonglong2*>(c_w + 2960 + j * 16);
        #pragma unroll
        for (int r = 0; r < 4; ++r) {
            ulonglong2 w = w3[r];
            acc3[2 * r + 0] = ffma2(p, w.x, acc3[2 * r + 0]);
            acc3[2 * r + 1] = ffma2(p, w.y, acc3[2 * r + 1]);
        }
    }
    #pragma unroll
    for (int t = 0; t < 8; ++t) acc3[t] = relu2(acc3[t]);

    float q0 = 0.0f, q1 = 0.0f;
    #pragma unroll 4
    for (int m = 0; m < 32; ++m) {
        ull a = 0ull;
        const ulonglong2* wg = reinterpret_cast<const ulonglong2*>(c_w + 3488 + m * 32);
        #pragma unroll
        for (int q = 0; q < 4; ++q) {
            ulonglong2 w = wg[q];
            a = ffma2(acc3[2 * q + 0], w.x, a);
            a = ffma2(acc3[2 * q + 1], w.y, a);
        }
        #pragma unroll
        for (int q = 0; q < 4; ++q) {
            ulonglong2 w = wg[4 + q];
            a = ffma2(so_p[2 * q + 0], w.x, a);
            a = ffma2(so_p[2 * q + 1], w.y, a);
        }
        float gg = relu_(hadd2(a) + c_w[4512 + m]);
        q0 = fmaf(gg, c_w[4544 + 2 * m + 0], q0);
        q1 = fmaf(gg, c_w[4544 + 2 * m + 1], q1);
    }

    int act = (int)xs.w;
    act = act < 0 ? 0 : (act > 1 ? 1 : act);
    out_q[row] = act ? (q1 + c_w[4609]) : (q0 + c_w[4608]);
}

extern "C" void kernel_launch(void* const* d_in, const int* in_sizes, int n_in,
                              void* d_out, int out_size)
{
    (void)in_sizes; (void)n_in; (void)out_size;

    static cudaStream_t s2 = nullptr;
    static cudaEvent_t evFork = nullptr, evJoin = nullptr;
    if (!s2) {
        cudaStreamCreateWithFlags(&s2, cudaStreamNonBlocking);
        cudaEventCreateWithFlags(&evFork, cudaEventDisableTiming);
        cudaEventCreateWithFlags(&evJoin, cudaEventDisableTiming);
    }

    void* dst = nullptr;
    void* src = nullptr;
    cudaGetSymbolAddress(&dst, c_w);
    cudaGetSymbolAddress(&src, g_blob);

    // Fork: pack + memcpy on s2, overlapped with hmma on the main stream.
    cudaEventRecord(evFork, 0);
    cudaStreamWaitEvent(s2, evFork, 0);

    pack_kernel<<<8, 256, 0, s2>>>(
        (const float*)d_in[2],  (const float*)d_in[3],
        (const float*)d_in[4],  (const float*)d_in[5],
        (const float*)d_in[6],  (const float*)d_in[7],
        (const float*)d_in[8],  (const float*)d_in[9],
        (const float*)d_in[10], (const float*)d_in[11],
        (const float*)d_in[12], (const float*)d_in[13],
        (const float*)d_in[14], (const float*)d_in[15],
        (const float*)d_in[16], (const float*)d_in[17]);
    cudaMemcpyAsync(dst, src, CW_TOTAL * sizeof(float),
                    cudaMemcpyDeviceToDevice, s2);
    cudaEventRecord(evJoin, s2);

    // Kernel A (tensor pipe) on the main stream, independent of c_w.
    hmma_kernel<<<1024, 128>>>(
        (const float*)d_in[0], (const int*)d_in[1],
        (const float*)d_in[2], (const float*)d_in[3],
        (const float*)d_in[4], (const float*)d_in[5],
        (const float*)d_in[6], (const float*)d_in[7]);

    // Join: tail needs both g_sum (main stream) and c_w (s2).
    cudaStreamWaitEvent(0, evJoin, 0);
    tail_kernel<<<256, 256>>>((const float*)d_in[0], (const int*)d_in[1],
                              (float*)d_out);
}

// round 14
// speedup vs baseline: 1.0403x; 1.0403x over previous
#include <cuda_runtime.h>
#include <cuda_fp16.h>

#define FULL 0xffffffffu
typedef unsigned long long ull;
typedef unsigned int uint;

__device__ __forceinline__ float relu_(float v) { return fmaxf(v, 0.0f); }

__device__ __forceinline__ ull ffma2(ull a, ull b, ull c) {
    ull d; asm("fma.rn.f32x2 %0, %1, %2, %3;" : "=l"(d) : "l"(a), "l"(b), "l"(c)); return d;
}
__device__ __forceinline__ ull fadd2(ull a, ull b) {
    ull d; asm("add.rn.f32x2 %0, %1, %2;" : "=l"(d) : "l"(a), "l"(b)); return d;
}
__device__ __forceinline__ ull pk2(float lo, float hi) {
    ull r; asm("mov.b64 %0, {%1, %2};" : "=l"(r) : "f"(lo), "f"(hi)); return r;
}
__device__ __forceinline__ void upk2(ull v, float& lo, float& hi) {
    asm("mov.b64 {%0, %1}, %2;" : "=f"(lo), "=f"(hi) : "l"(v));
}
__device__ __forceinline__ ull relu2(ull v) {
    float lo, hi; upk2(v, lo, hi);
    return pk2(fmaxf(lo, 0.0f), fmaxf(hi, 0.0f));
}
__device__ __forceinline__ float hadd2(ull v) {
    float lo, hi; upk2(v, lo, hi); return lo + hi;
}

// fp16x2 pack (e0 -> lower 16 bits)
__device__ __forceinline__ uint pack_f16(float e0, float e1) {
    __half2 h = __floats2half2_rn(e0, e1);
    return *reinterpret_cast<uint*>(&h);
}
// relu in the fp16x2 domain
__device__ __forceinline__ uint hrelu2(uint v) {
    uint r; asm("max.f16x2 %0, %1, %2;" : "=r"(r) : "r"(v), "r"(0u)); return r;
}
__device__ __forceinline__ uint packrelu_f16(float e0, float e1) {
    return hrelu2(pack_f16(e0, e1));
}

// m16n8k16 fp16 MMA, in-place fp32 accumulate.
__device__ __forceinline__ void mma_f16(float4& d, uint a0, uint a1, uint a2, uint a3,
                                        uint b0, uint b1) {
    asm volatile(
        "mma.sync.aligned.m16n8k16.row.col.f32.f16.f16.f32 "
        "{%0,%1,%2,%3}, {%4,%5,%6,%7}, {%8,%9}, {%0,%1,%2,%3};"
        : "+f"(d.x), "+f"(d.y), "+f"(d.z), "+f"(d.w)
        : "r"(a0), "r"(a1), "r"(a2), "r"(a3), "r"(b0), "r"(b1));
}
// m16n8k16 fp16 MMA, SEPARATE C operand: D = A*B + C.
__device__ __forceinline__ float4 mma_f16_c(uint a0, uint a1, uint a2, uint a3,
                                            uint b0, uint b1,
                                            float c0, float c1, float c2, float c3) {
    float4 d;
    asm volatile(
        "mma.sync.aligned.m16n8k16.row.col.f32.f16.f16.f32 "
        "{%0,%1,%2,%3}, {%4,%5,%6,%7}, {%8,%9}, {%10,%11,%12,%13};"
        : "=f"(d.x), "=f"(d.y), "=f"(d.z), "=f"(d.w)
        : "r"(a0), "r"(a1), "r"(a2), "r"(a3), "r"(b0), "r"(b1),
          "f"(c0), "f"(c1), "f"(c2), "f"(c3));
    return d;
}

// ---------------- constant blob (tail weights; layout as rounds 7-13) ----------------
#define CW_TOTAL 4624
__constant__ __align__(16) float c_w[CW_TOTAL];
__device__   __align__(16) float g_blob[CW_TOTAL];

#define NROWS 65536
__device__ __align__(16) ull g_sum[NROWS * 8];

__global__ void pack_kernel(const float* __restrict__ oW1, const float* __restrict__ ob1,
                            const float* __restrict__ oW2, const float* __restrict__ ob2,
                            const float* __restrict__ oW3, const float* __restrict__ ob3,
                            const float* __restrict__ sW1, const float* __restrict__ sb1,
                            const float* __restrict__ sW2, const float* __restrict__ sb2,
                            const float* __restrict__ sW3, const float* __restrict__ sb3,
                            const float* __restrict__ gW1, const float* __restrict__ gb1,
                            const float* __restrict__ gW2, const float* __restrict__ gb2)
{
    const int gt = blockIdx.x * 256 + threadIdx.x;   // 0..2047
    if (gt < 128) {
        int tp = gt >> 3, d = (gt >> 1) & 3, e = gt & 1;
        g_blob[gt]        = oW1[d * 32 + 2 * tp + e];
        g_blob[1744 + gt] = sW1[d * 32 + 2 * tp + e];
    }
    if (gt >= 128 && gt < 160) {
        int t = gt - 128;
        g_blob[128 + t]  = ob1[t];
        g_blob[1184 + t] = ob2[t];
        g_blob[1872 + t] = sb1[t];
        g_blob[2928 + t] = sb2[t];
        g_blob[4512 + t] = gb1[t];
    }
    if (gt >= 160 && gt < 176) { g_blob[1728 + gt - 160] = ob3[gt - 160]; }
    if (gt >= 176 && gt < 192) { g_blob[3472 + gt - 176] = sb3[gt - 176]; }
    if (gt >= 192 && gt < 256) { g_blob[4544 + gt - 192] = gW2[gt - 192]; }
    if (gt >= 256 && gt < 258) { g_blob[4608 + gt - 256] = gb2[gt - 256]; }
    if (gt < 1024) {
        int j = gt >> 5, i = gt & 31;
        g_blob[160  + j * 32 + i] = oW2[i * 32 + j];
        g_blob[1904 + j * 32 + i] = sW2[i * 32 + j];
        g_blob[3488 + j * 32 + i] = gW1[i * 32 + j];
    }
    if (gt >= 1024 && gt < 1536) {
        int idx = gt - 1024;
        g_blob[1216 + idx] = oW3[idx];
        g_blob[2960 + idx] = sW3[idx];
    }
}

// ---------------- Kernel A: other-agent MLP on TENSOR pipe (fp16, 32 MMA/row) -------
// Occ-3 (170-reg cap) with both m-chains phase-interleaved: 2 independent MMA
// streams per warp x 3 warps/SMSP = 6 concurrent chains.
__global__ __launch_bounds__(128, 3)
void hmma_kernel(const float* __restrict__ x,
                 const int*   __restrict__ selp,
                 const float* __restrict__ oW1, const float* __restrict__ ob1,
                 const float* __restrict__ oW2, const float* __restrict__ ob2,
                 const float* __restrict__ oW3, const float* __restrict__ ob3)
{
    const int lane  = threadIdx.x & 31;
    const int warp  = threadIdx.x >> 5;
    const int gwarp = blockIdx.x * 4 + warp;      // 0..4095
    const int g  = lane >> 2;                      // 0..7
    const int tc = lane & 3;                       // 0..3
    const int sel = selp[0];
    const uint Z = 0u;

    // ---- B fragments (single fp16) ----
    uint B1[4];
    #pragma unroll
    for (int n = 0; n < 4; ++n) {
        float wa = 0.0f, wb = 0.0f;
        if (tc < 2) {
            wa = oW1[(2 * tc) * 32 + 8 * n + g];
            wb = oW1[(2 * tc + 1) * 32 + 8 * n + g];
        }
        B1[n] = pack_f16(wa, wb);
    }
    uint B2[4][2][2];
    #pragma unroll
    for (int n = 0; n < 4; ++n) {
        #pragma unroll
        for (int ks = 0; ks < 2; ++ks) {
            int c  = 8 * n + g;
            int k0 = 16 * ks + 2 * tc;
            B2[n][ks][0] = pack_f16(oW2[k0 * 32 + c],       oW2[(k0 + 1) * 32 + c]);
            B2[n][ks][1] = pack_f16(oW2[(k0 + 8) * 32 + c], oW2[(k0 + 9) * 32 + c]);
        }
    }
    uint B3[2][2][2];
    #pragma unroll
    for (int n = 0; n < 2; ++n) {
        #pragma unroll
        for (int ks = 0; ks < 2; ++ks) {
            int c  = 8 * n + g;
            int k0 = 16 * ks + 2 * tc;
            B3[n][ks][0] = pack_f16(oW3[k0 * 16 + c],       oW3[(k0 + 1) * 16 + c]);
            B3[n][ks][1] = pack_f16(oW3[(k0 + 8) * 16 + c], oW3[(k0 + 9) * 16 + c]);
        }
    }
    float2 bz1[4], bz2[4], bz3[2];
    #pragma unroll
    for (int n = 0; n < 4; ++n) {
        bz1[n] = *reinterpret_cast<const float2*>(ob1 + 8 * n + 2 * tc);
        bz2[n] = *reinterpret_cast<const float2*>(ob2 + 8 * n + 2 * tc);
    }
    #pragma unroll
    for (int n = 0; n < 2; ++n)
        bz3[n] = *reinterpret_cast<const float2*>(ob3 + 8 * n + 2 * tc);

    // per-lane x offsets (within a row of 128 floats)
    const int offA0 = (g) * 4 + (tc & 1) * 2;
    const int offB0 = (8 + g) * 4 + (tc & 1) * 2;
    const int offA1 = (16 + g) * 4 + (tc & 1) * 2;
    const int offB1 = (24 + g) * 4 + (tc & 1) * 2;

    const float* xr = x + (size_t)(gwarp * 16) * 128;

    // prefetch first row
    float2 nA0 = *reinterpret_cast<const float2*>(xr + offA0);
    float2 nB0 = *reinterpret_cast<const float2*>(xr + offB0);
    float2 nA1 = *reinterpret_cast<const float2*>(xr + offA1);
    float2 nB1 = *reinterpret_cast<const float2*>(xr + offB1);

    // ---- persistent row loop: 16 rows per warp ----
    for (int it = 0; it < 16; ++it) {
        const int row = gwarp * 16 + it;
        float2 cA[2] = { nA0, nA1 };
        float2 cB[2] = { nB0, nB1 };
        if (it < 15) {
            const float* xn = xr + 128;
            nA0 = *reinterpret_cast<const float2*>(xn + offA0);
            nB0 = *reinterpret_cast<const float2*>(xn + offB0);
            nA1 = *reinterpret_cast<const float2*>(xn + offA1);
            nB1 = *reinterpret_cast<const float2*>(xn + offB1);
        }
        xr += 128;

        // ---- phase-interleaved: both m-chains advance together ----
        uint a0[2], a1[2];
        #pragma unroll
        for (int m = 0; m < 2; ++m) {
            a0[m] = pack_f16(cA[m].x, cA[m].y);
            a1[m] = pack_f16(cB[m].x, cB[m].y);
        }

        // G1 (both m): bias via separate C
        float4 D1[2][4];
        #pragma unroll
        for (int m = 0; m < 2; ++m)
            #pragma unroll
            for (int n = 0; n < 4; ++n)
                D1[m][n] = mma_f16_c(a0[m], a1[m], Z, Z, B1[n], Z,
                                     bz1[n].x, bz1[n].y, bz1[n].x, bz1[n].y);

        // G2 ks=0 (both m)
        uint A[2][4];
        #pragma unroll
        for (int m = 0; m < 2; ++m) {
            A[m][0] = packrelu_f16(D1[m][0].x, D1[m][0].y);
            A[m][1] = packrelu_f16(D1[m][0].z, D1[m][0].w);
            A[m][2] = packrelu_f16(D1[m][1].x, D1[m][1].y);
            A[m][3] = packrelu_f16(D1[m][1].z, D1[m][1].w);
        }
        float4 D2[2][4];
        #pragma unroll
        for (int m = 0; m < 2; ++m)
            #pragma unroll
            for (int n = 0; n < 4; ++n)
                D2[m][n] = mma_f16_c(A[m][0], A[m][1], A[m][2], A[m][3],
                                     B2[n][0][0], B2[n][0][1],
                                     bz2[n].x, bz2[n].y, bz2[n].x, bz2[n].y);
        // G2 ks=1 (both m)
        #pragma unroll
        for (int m = 0; m < 2; ++m) {
            A[m][0] = packrelu_f16(D1[m][2].x, D1[m][2].y);
            A[m][1] = packrelu_f16(D1[m][2].z, D1[m][2].w);
            A[m][2] = packrelu_f16(D1[m][3].x, D1[m][3].y);
            A[m][3] = packrelu_f16(D1[m][3].z, D1[m][3].w);
        }
        #pragma unroll
        for (int m = 0; m < 2; ++m)
            #pragma unroll
            for (int n = 0; n < 4; ++n)
                mma_f16(D2[m][n], A[m][0], A[m][1], A[m][2], A[m][3],
                        B2[n][1][0], B2[n][1][1]);

        // G3 ks=0 (both m)
        #pragma unroll
        for (int m = 0; m < 2; ++m) {
            A[m][0] = packrelu_f16(D2[m][0].x, D2[m][0].y);
            A[m][1] = packrelu_f16(D2[m][0].z, D2[m][0].w);
            A[m][2] = packrelu_f16(D2[m][1].x, D2[m][1].y);
            A[m][3] = packrelu_f16(D2[m][1].z, D2[m][1].w);
        }
        float4 D3[2][2];
        #pragma unroll
        for (int m = 0; m < 2; ++m)
            #pragma unroll
            for (int n = 0; n < 2; ++n)
                D3[m][n] = mma_f16_c(A[m][0], A[m][1], A[m][2], A[m][3],
                                     B3[n][0][0], B3[n][0][1],
                                     bz3[n].x, bz3[n].y, bz3[n].x, bz3[n].y);
        // G3 ks=1 (both m)
        #pragma unroll
        for (int m = 0; m < 2; ++m) {
            A[m][0] = packrelu_f16(D2[m][2].x, D2[m][2].y);
            A[m][1] = packrelu_f16(D2[m][2].z, D2[m][2].w);
            A[m][2] = packrelu_f16(D2[m][3].x, D2[m][3].y);
            A[m][3] = packrelu_f16(D2[m][3].z, D2[m][3].w);
        }
        #pragma unroll
        for (int m = 0; m < 2; ++m)
            #pragma unroll
            for (int n = 0; n < 2; ++n)
                mma_f16(D3[m][n], A[m][0], A[m][1], A[m][2], A[m][3],
                        B3[n][1][0], B3[n][1][1]);

        // epilogue: relu, mask selected agent, accumulate over m
        float v00 = 0.f, v01 = 0.f, v10 = 0.f, v11 = 0.f;
        #pragma unroll
        for (int m = 0; m < 2; ++m) {
            float mk0 = (m * 16 + g == sel) ? 0.0f : 1.0f;
            float mk1 = (m * 16 + 8 + g == sel) ? 0.0f : 1.0f;
            v00 += relu_(D3[m][0].x) * mk0 + relu_(D3[m][0].z) * mk1;
            v01 += relu_(D3[m][0].y) * mk0 + relu_(D3[m][0].w) * mk1;
            v10 += relu_(D3[m][1].x) * mk0 + relu_(D3[m][1].z) * mk1;
            v11 += relu_(D3[m][1].y) * mk0 + relu_(D3[m][1].w) * mk1;
        }

        ull p0 = pk2(v00, v01);
        ull p1 = pk2(v10, v11);
        #pragma unroll
        for (int off = 4; off < 32; off <<= 1) {
            p0 = fadd2(p0, __shfl_xor_sync(FULL, p0, off));
            p1 = fadd2(p1, __shfl_xor_sync(FULL, p1, off));
        }
        if (lane < 4) {
            g_sum[(size_t)row * 8 + tc]     = p0;
            g_sum[(size_t)row * 8 + 4 + tc] = p1;
        }
    }
}

// ---------------- Kernel B: tail (unchanged, full fp32) ----------------
__global__ __launch_bounds__(256)
void tail_kernel(const float* __restrict__ x,
                 const int*   __restrict__ selp,
                 float* __restrict__ out_q)
{
    const int row = blockIdx.x * 256 + threadIdx.x;
    const int sel = selp[0];

    const float4 xs = reinterpret_cast<const float4*>(x)[row * 32 + sel];

    ull so_p[8];
    {
        const ulonglong2* src = reinterpret_cast<const ulonglong2*>(g_sum + (size_t)row * 8);
        #pragma unroll
        for (int r = 0; r < 4; ++r) {
            ulonglong2 v = src[r];
            so_p[2 * r + 0] = v.x;
            so_p[2 * r + 1] = v.y;
        }
    }

    ull xd0 = pk2(xs.x, xs.x), xd1 = pk2(xs.y, xs.y);
    ull xd2 = pk2(xs.z, xs.z), xd3 = pk2(xs.w, xs.w);
    ull h1[16];
    {
        const ulonglong2* w1 = reinterpret_cast<const ulonglong2*>(c_w + 1744);
        const ull* b1 = reinterpret_cast<const ull*>(c_w + 1872);
        #pragma unroll
        for (int t = 0; t < 16; ++t) {
            ulonglong2 wA = w1[2 * t + 0];
            ulonglong2 wB = w1[2 * t + 1];
            ull a = ffma2(xd0, wA.x, b1[t]);
            a = ffma2(xd1, wA.y, a);
            a = ffma2(xd2, wB.x, a);
            a = ffma2(xd3, wB.y, a);
            h1[t] = relu2(a);
        }
    }

    ull acc3[8];
    {
        const ull* b3 = reinterpret_cast<const ull*>(c_w + 3472);
        #pragma unroll
        for (int t = 0; t < 8; ++t) acc3[t] = b3[t];
    }
    #pragma unroll 4
    for (int j = 0; j < 32; ++j) {
        ull a = 0ull;
        const ulonglong2* w2 = reinterpret_cast<const ulonglong2*>(c_w + 1904 + j * 32);
        #pragma unroll
        for (int q = 0; q < 8; ++q) {
            ulonglong2 w = w2[q];
            a = ffma2(h1[2 * q + 0], w.x, a);
            a = ffma2(h1[2 * q + 1], w.y, a);
        }
        float s = relu_(hadd2(a) + c_w[2928 + j]);
        ull p = pk2(s, s);
        const ulonglong2* w3 = reinterpret_cast<const ulonglong2*>(c_w + 2960 + j * 16);
        #pragma unroll
        for (int r = 0; r < 4; ++r) {
            ulonglong2 w = w3[r];
            acc3[2 * r + 0] = ffma2(p, w.x, acc3[2 * r + 0]);
            acc3[2 * r + 1] = ffma2(p, w.y, acc3[2 * r + 1]);
        }
    }
    #pragma unroll
    for (int t = 0; t < 8; ++t) acc3[t] = relu2(acc3[t]);

    float q0 = 0.0f, q1 = 0.0f;
    #pragma unroll 4
    for (int m = 0; m < 32; ++m) {
        ull a = 0ull;
        const ulonglong2* wg = reinterpret_cast<const ulonglong2*>(c_w + 3488 + m * 32);
        #pragma unroll
        for (int q = 0; q < 4; ++q) {
            ulonglong2 w = wg[q];
            a = ffma2(acc3[2 * q + 0], w.x, a);
            a = ffma2(acc3[2 * q + 1], w.y, a);
        }
        #pragma unroll
        for (int q = 0; q < 4; ++q) {
            ulonglong2 w = wg[4 + q];
            a = ffma2(so_p[2 * q + 0], w.x, a);
            a = ffma2(so_p[2 * q + 1], w.y, a);
        }
        float gg = relu_(hadd2(a) + c_w[4512 + m]);
        q0 = fmaf(gg, c_w[4544 + 2 * m + 0], q0);
        q1 = fmaf(gg, c_w[4544 + 2 * m + 1], q1);
    }

    int act = (int)xs.w;
    act = act < 0 ? 0 : (act > 1 ? 1 : act);
    out_q[row] = act ? (q1 + c_w[4609]) : (q0 + c_w[4608]);
}

extern "C" void kernel_launch(void* const* d_in, const int* in_sizes, int n_in,
                              void* d_out, int out_size)
{
    (void)in_sizes; (void)n_in; (void)out_size;

    static cudaStream_t s2 = nullptr;
    static cudaEvent_t evFork = nullptr, evJoin = nullptr;
    if (!s2) {
        cudaStreamCreateWithFlags(&s2, cudaStreamNonBlocking);
        cudaEventCreateWithFlags(&evFork, cudaEventDisableTiming);
        cudaEventCreateWithFlags(&evJoin, cudaEventDisableTiming);
    }

    void* dst = nullptr;
    void* src = nullptr;
    cudaGetSymbolAddress(&dst, c_w);
    cudaGetSymbolAddress(&src, g_blob);

    // Fork: pack + memcpy on s2, overlapped with hmma on the main stream.
    cudaEventRecord(evFork, 0);
    cudaStreamWaitEvent(s2, evFork, 0);

    pack_kernel<<<8, 256, 0, s2>>>(
        (const float*)d_in[2],  (const float*)d_in[3],
        (const float*)d_in[4],  (const float*)d_in[5],
        (const float*)d_in[6],  (const float*)d_in[7],
        (const float*)d_in[8],  (const float*)d_in[9],
        (const float*)d_in[10], (const float*)d_in[11],
        (const float*)d_in[12], (const float*)d_in[13],
        (const float*)d_in[14], (const float*)d_in[15],
        (const float*)d_in[16], (const float*)d_in[17]);
    cudaMemcpyAsync(dst, src, CW_TOTAL * sizeof(float),
                    cudaMemcpyDeviceToDevice, s2);
    cudaEventRecord(evJoin, s2);

    // Kernel A (tensor pipe) on the main stream, independent of c_w.
    hmma_kernel<<<1024, 128>>>(
        (const float*)d_in[0], (const int*)d_in[1],
        (const float*)d_in[2], (const float*)d_in[3],
        (const float*)d_in[4], (const float*)d_in[5],
        (const float*)d_in[6], (const float*)d_in[7]);

    // Join: tail needs both g_sum (main stream) and c_w (s2).
    cudaStreamWaitEvent(0, evJoin, 0);
    tail_kernel<<<256, 256>>>((const float*)d_in[0], (const int*)d_in[1],
                              (float*)d_out);
}